// round 11
// baseline (speedup 1.0000x reference)
#include <cuda_runtime.h>
#include <cuda_bf16.h>
#include <math.h>

#define B_  8
#define SQ_ 2048
#define SK_ 2048
#define D_  1024
#define DV_ 1024
#define SCALE (1.0f/32.0f)

#define BM 128
#define BN 128
#define BK 16
#define AST 20    // A/W smem row stride (words): conflict-free fragment loads
#define VST 136   // V smem row stride (words): conflict-free b-frag loads

__device__ __forceinline__ unsigned f2tf(float x) {
    unsigned u;
    asm("cvt.rna.tf32.f32 %0, %1;" : "=r"(u) : "f"(x));
    return u;
}
__device__ __forceinline__ unsigned u2tf(unsigned r) { return f2tf(__uint_as_float(r)); }

__device__ __forceinline__ void mma_tf32(float c[4], const unsigned a[4], const unsigned b[2]) {
    asm volatile(
        "mma.sync.aligned.m16n8k8.row.col.f32.tf32.tf32.f32 "
        "{%0,%1,%2,%3}, {%4,%5,%6,%7}, {%8,%9}, {%0,%1,%2,%3};"
        : "+f"(c[0]), "+f"(c[1]), "+f"(c[2]), "+f"(c[3])
        : "r"(a[0]), "r"(a[1]), "r"(a[2]), "r"(a[3]), "r"(b[0]), "r"(b[1]));
}

__device__ __forceinline__ void ldsm4(unsigned& r0, unsigned& r1, unsigned& r2, unsigned& r3,
                                      unsigned addr) {
    asm volatile("ldmatrix.sync.aligned.m8n8.x4.shared.b16 {%0,%1,%2,%3}, [%4];"
                 : "=r"(r0), "=r"(r1), "=r"(r2), "=r"(r3) : "r"(addr));
}

__device__ __forceinline__ unsigned smem_u32(const void* p) {
    return (unsigned)__cvta_generic_to_shared(p);
}

__device__ __forceinline__ void cpa16(void* smem, const void* gmem) {
    unsigned s = (unsigned)__cvta_generic_to_shared(smem);
    asm volatile("cp.async.ca.shared.global [%0], [%1], 16;" :: "r"(s), "l"(gmem));
}
__device__ __forceinline__ void cpa_commit() { asm volatile("cp.async.commit_group;"); }
__device__ __forceinline__ void cpa_wait1()  { asm volatile("cp.async.wait_group 1;"); }
__device__ __forceinline__ void cpa_wait0()  { asm volatile("cp.async.wait_group 0;"); }

// ---------------------------------------------------------------------------
// Kernel 1: raw scores S = (Q @ K^T) * scale (tf32 MMA + ldmatrix frags).
// 128x128 tile, 8 warps as 2(m)x4(n), warp tile 64x32. 2-stage cp.async.
// ---------------------------------------------------------------------------
__global__ __launch_bounds__(256, 2) void scores_kernel(
    const float* __restrict__ Q, const float* __restrict__ K,
    const int* __restrict__ qlens, const int* __restrict__ klens,
    float* __restrict__ Sout)
{
    const int b  = blockIdx.z;
    const int q0 = blockIdx.y * BM;
    const int k0 = blockIdx.x * BN;
    const int qlen = qlens[b];
    const int klen = klens[b];
    if (q0 >= qlen || k0 >= klen || k0 > q0 + BM - 1) return;

    __shared__ float As[2][BM][AST];
    __shared__ float Bs[2][BN][AST];

    const int tid  = threadIdx.x;
    const int lane = tid & 31;
    const int wid  = tid >> 5;          // 0..7
    const int wm   = (wid & 1) * 64;
    const int wn   = (wid >> 1) * 32;
    const int g    = lane >> 2;
    const int t    = lane & 3;
    const int sub  = lane >> 3;         // 0..3  (ldmatrix tile index)
    const int j8   = lane & 7;          // row within tile

    // ldmatrix per-lane base addresses (bytes):
    //   A tiles: {m, k}, {m+8, k}, {m, k+4}, {m+8, k+4}
    //   B tiles: {n, k}, {n, k+4}, {n+8, k}, {n+8, k+4}
    const unsigned aBase = smem_u32(As) +
        ((unsigned)((wm + (sub & 1) * 8 + j8) * AST + (sub >> 1) * 4)) * 4u;
    const unsigned bBase = smem_u32(Bs) +
        ((unsigned)((wn + (sub >> 1) * 8 + j8) * AST + (sub & 1) * 4)) * 4u;
    const unsigned stgA = BM * AST * 4u;   // bytes per pipeline stage

    const float* Qb = Q + ((size_t)b * SQ_ + q0) * D_;
    const float* Kb = K + ((size_t)b * SK_ + k0) * D_;

    const int lrow0 = tid >> 2;                 // 0..63; chunk j: row = lrow0 + 64*j
    const int lc4   = (tid & 3) * 4;

#define ISSUE_S(s, it)                                                     \
    {                                                                      \
        const int kofs = (it) * BK;                                        \
        _Pragma("unroll")                                                  \
        for (int j = 0; j < 2; ++j) {                                      \
            const int row = lrow0 + 64 * j;                                \
            cpa16(&As[s][row][lc4], Qb + (size_t)row * D_ + kofs + lc4);   \
            cpa16(&Bs[s][row][lc4], Kb + (size_t)row * D_ + kofs + lc4);   \
        }                                                                  \
        cpa_commit();                                                      \
    }

    const int NT = D_ / BK;   // 64
    ISSUE_S(0, 0)
    ISSUE_S(1, 1)

    float acc[4][4][4];
#pragma unroll
    for (int i = 0; i < 4; ++i)
#pragma unroll
        for (int j = 0; j < 4; ++j)
#pragma unroll
            for (int c = 0; c < 4; ++c) acc[i][j][c] = 0.f;

    for (int it = 0; it < NT; ++it) {
        if (it < NT - 1) cpa_wait1(); else cpa_wait0();
        __syncthreads();
        const unsigned offA = (it & 1) ? stgA : 0u;
#pragma unroll
        for (int ks = 0; ks < 2; ++ks) {
            unsigned a[4][4], bb[4][2];
#pragma unroll
            for (int mf = 0; mf < 4; ++mf) {
                unsigned r0, r1, r2, r3;
                ldsm4(r0, r1, r2, r3,
                      aBase + offA + (unsigned)((mf * 16 * AST + ks * 8) * 4));
                a[mf][0] = u2tf(r0); a[mf][1] = u2tf(r1);
                a[mf][2] = u2tf(r2); a[mf][3] = u2tf(r3);
            }
#pragma unroll
            for (int nfp = 0; nfp < 2; ++nfp) {
                unsigned r0, r1, r2, r3;
                ldsm4(r0, r1, r2, r3,
                      bBase + offA + (unsigned)((nfp * 16 * AST + ks * 8) * 4));
                bb[2*nfp][0]   = u2tf(r0); bb[2*nfp][1]   = u2tf(r1);
                bb[2*nfp+1][0] = u2tf(r2); bb[2*nfp+1][1] = u2tf(r3);
            }
#pragma unroll
            for (int mf = 0; mf < 4; ++mf)
#pragma unroll
                for (int nf = 0; nf < 4; ++nf)
                    mma_tf32(acc[mf][nf], a[mf], bb[nf]);
        }
        __syncthreads();
        if (it + 2 < NT) ISSUE_S((it & 1), it + 2)
    }

    float* Sp = Sout + ((size_t)b * SQ_ + q0) * SK_ + k0;
#pragma unroll
    for (int mf = 0; mf < 4; ++mf) {
        const int r0 = wm + mf * 16 + g;
#pragma unroll
        for (int nf = 0; nf < 4; ++nf) {
            const int c0 = wn + nf * 8 + 2 * t;
            float2 v0 = make_float2(acc[mf][nf][0] * SCALE, acc[mf][nf][1] * SCALE);
            float2 v1 = make_float2(acc[mf][nf][2] * SCALE, acc[mf][nf][3] * SCALE);
            *(float2*)(Sp + (size_t)r0 * SK_ + c0)       = v0;
            *(float2*)(Sp + (size_t)(r0 + 8) * SK_ + c0) = v1;
        }
    }
#undef ISSUE_S
}

// ---------------------------------------------------------------------------
// Kernel 2: in-place masked softmax per row; reads only the valid prefix,
// zero-writes everything else.
// ---------------------------------------------------------------------------
__global__ __launch_bounds__(256) void softmax_kernel(
    float* __restrict__ Wio,
    const int* __restrict__ qlens, const int* __restrict__ klens)
{
    const int q = blockIdx.x;
    const int b = blockIdx.y;
    const int tid = threadIdx.x;
    const int lane = tid & 31;
    const int wid = tid >> 5;
    float* row = Wio + ((size_t)b * SQ_ + q) * SK_;

    const int qlen = qlens[b];
    const int klen = klens[b];

    if (q >= qlen) {
        float4 z = make_float4(0.f, 0.f, 0.f, 0.f);
        for (int j = tid; j < SK_ / 4; j += 256) ((float4*)row)[j] = z;
        return;
    }

    const int kk  = min(klen, q + 1);
    const int kq4 = (kk + 3) >> 2;

    __shared__ float buf[SK_];
    __shared__ float red[8];

    float m = -3.402823466e38f;
    for (int j = tid; j < kq4; j += 256) {
        float4 s = ((const float4*)row)[j];
        ((float4*)buf)[j] = s;
        int base = j * 4;
        if (base + 0 < kk) m = fmaxf(m, s.x);
        if (base + 1 < kk) m = fmaxf(m, s.y);
        if (base + 2 < kk) m = fmaxf(m, s.z);
        if (base + 3 < kk) m = fmaxf(m, s.w);
    }
#pragma unroll
    for (int o = 16; o > 0; o >>= 1) m = fmaxf(m, __shfl_xor_sync(0xffffffffu, m, o));
    if (lane == 0) red[wid] = m;
    __syncthreads();
    m = red[0];
#pragma unroll
    for (int w = 1; w < 8; ++w) m = fmaxf(m, red[w]);
    __syncthreads();

    float sum = 0.f;
    for (int j = tid; j < kq4; j += 256) {
        int base = j * 4;
        float4 s = ((const float4*)buf)[j];
        float4 e;
        e.x = (base + 0 < kk) ? __expf(s.x - m) : 0.f;
        e.y = (base + 1 < kk) ? __expf(s.y - m) : 0.f;
        e.z = (base + 2 < kk) ? __expf(s.z - m) : 0.f;
        e.w = (base + 3 < kk) ? __expf(s.w - m) : 0.f;
        ((float4*)buf)[j] = e;
        sum += e.x + e.y + e.z + e.w;
    }
#pragma unroll
    for (int o = 16; o > 0; o >>= 1) sum += __shfl_xor_sync(0xffffffffu, sum, o);
    if (lane == 0) red[wid] = sum;
    __syncthreads();
    float tot = red[0];
#pragma unroll
    for (int w = 1; w < 8; ++w) tot += red[w];
    const float inv = 1.f / tot;

    for (int j = tid; j < kq4; j += 256) {
        float4 e = ((const float4*)buf)[j];
        e.x *= inv; e.y *= inv; e.z *= inv; e.w *= inv;
        ((float4*)row)[j] = e;
    }
    float4 z = make_float4(0.f, 0.f, 0.f, 0.f);
    for (int j = kq4 + tid; j < SK_ / 4; j += 256) ((float4*)row)[j] = z;
}

// ---------------------------------------------------------------------------
// Kernel 3: context = W @ V (tf32 MMA; ldmatrix for W frags, scalar for V).
// 8 warps, warp tile 64x32; 2-stage pipeline; K clamped to valid prefix.
// ---------------------------------------------------------------------------
__global__ __launch_bounds__(256, 2) void context_kernel(
    const float* __restrict__ W, const float* __restrict__ V,
    const int* __restrict__ qlens, const int* __restrict__ klens,
    float* __restrict__ C)
{
    const int b  = blockIdx.z;
    const int q0 = blockIdx.y * BM;
    const int v0 = blockIdx.x * BN;
    const int qlen = qlens[b];
    const int klen = klens[b];

    const int tid  = threadIdx.x;
    float* Cb = C + ((size_t)b * SQ_ + q0) * DV_ + v0;

    if (q0 >= qlen) {
        float4 z = make_float4(0.f, 0.f, 0.f, 0.f);
        for (int idx = tid; idx < BM * BN / 4; idx += 256) {
            const int r = idx / (BN / 4);
            const int c = (idx % (BN / 4)) * 4;
            *(float4*)(Cb + (size_t)r * DV_ + c) = z;
        }
        return;
    }

    __shared__ float Ws[2][BM][AST];
    __shared__ float Vs[2][BK][VST];

    const int lane = tid & 31;
    const int wid  = tid >> 5;
    const int wm   = (wid & 1) * 64;
    const int wn   = (wid >> 1) * 32;
    const int g    = lane >> 2;
    const int t    = lane & 3;
    const int sub  = lane >> 3;
    const int j8   = lane & 7;

    const unsigned aBase = smem_u32(Ws) +
        ((unsigned)((wm + (sub & 1) * 8 + j8) * AST + (sub >> 1) * 4)) * 4u;
    const unsigned stgA = BM * AST * 4u;

    const float* Wb = W + ((size_t)b * SQ_ + q0) * SK_;
    const float* Vb = V + (size_t)b * SK_ * DV_ + v0;

    const int lrow0 = tid >> 2;             // 0..63; W rows lrow0 + 64*j
    const int lc4   = (tid & 3) * 4;
    const int vk0   = tid >> 5;             // 0..7; V k-rows vk0 + 8*j
    const int vn4   = (tid & 31) * 4;

#define ISSUE_C(s, it)                                                       \
    {                                                                        \
        const int kofs = (it) * BK;                                          \
        _Pragma("unroll")                                                    \
        for (int j = 0; j < 2; ++j) {                                        \
            const int row = lrow0 + 64 * j;                                  \
            cpa16(&Ws[s][row][lc4], Wb + (size_t)row * SK_ + kofs + lc4);    \
        }                                                                    \
        _Pragma("unroll")                                                    \
        for (int j = 0; j < 2; ++j) {                                        \
            const int kr = vk0 + 8 * j;                                      \
            cpa16(&Vs[s][kr][vn4], Vb + (size_t)(kofs + kr) * DV_ + vn4);    \
        }                                                                    \
        cpa_commit();                                                        \
    }

    const int kend = min(klen, q0 + BM);
    const int NT   = (kend + BK - 1) / BK;   // >= 1

    ISSUE_C(0, 0)
    if (NT > 1) ISSUE_C(1, 1)

    float acc[4][4][4];
#pragma unroll
    for (int i = 0; i < 4; ++i)
#pragma unroll
        for (int j = 0; j < 4; ++j)
#pragma unroll
            for (int c = 0; c < 4; ++c) acc[i][j][c] = 0.f;

    for (int it = 0; it < NT; ++it) {
        if (it < NT - 1) cpa_wait1(); else cpa_wait0();
        __syncthreads();
        const int buf = it & 1;
        const unsigned offA = buf ? stgA : 0u;
#pragma unroll
        for (int ks = 0; ks < 2; ++ks) {
            const int kc = ks * 8 + t;
            unsigned a[4][4], bb[4][2];
#pragma unroll
            for (int mf = 0; mf < 4; ++mf) {
                unsigned r0, r1, r2, r3;
                ldsm4(r0, r1, r2, r3,
                      aBase + offA + (unsigned)((mf * 16 * AST + ks * 8) * 4));
                a[mf][0] = u2tf(r0); a[mf][1] = u2tf(r1);
                a[mf][2] = u2tf(r2); a[mf][3] = u2tf(r3);
            }
#pragma unroll
            for (int nf = 0; nf < 4; ++nf) {
                const int col = wn + nf * 8;
                bb[nf][0] = f2tf(Vs[buf][kc][col + g]);
                bb[nf][1] = f2tf(Vs[buf][kc + 4][col + g]);
            }
#pragma unroll
            for (int mf = 0; mf < 4; ++mf)
#pragma unroll
                for (int nf = 0; nf < 4; ++nf)
                    mma_tf32(acc[mf][nf], a[mf], bb[nf]);
        }
        __syncthreads();
        if (it + 2 < NT) ISSUE_C(buf, it + 2)
    }

#pragma unroll
    for (int mf = 0; mf < 4; ++mf) {
        const int r0 = wm + mf * 16 + g;
#pragma unroll
        for (int nf = 0; nf < 4; ++nf) {
            const int c0 = wn + nf * 8 + 2 * t;
            float2 v0r = make_float2(acc[mf][nf][0], acc[mf][nf][1]);
            float2 v1r = make_float2(acc[mf][nf][2], acc[mf][nf][3]);
            *(float2*)(Cb + (size_t)r0 * DV_ + c0)       = v0r;
            *(float2*)(Cb + (size_t)(r0 + 8) * DV_ + c0) = v1r;
        }
    }
#undef ISSUE_C
}

// ---------------------------------------------------------------------------
extern "C" void kernel_launch(void* const* d_in, const int* in_sizes, int n_in,
                              void* d_out, int out_size)
{
    const float* Q = (const float*)d_in[0];
    const float* K = (const float*)d_in[1];
    const float* V = (const float*)d_in[2];
    const int* qlens = (const int*)d_in[3];
    const int* klens = (const int*)d_in[4];

    float* ctx = (float*)d_out;
    float* wts = (float*)d_out + (size_t)B_ * SQ_ * DV_;

    {
        dim3 grid(SK_ / BN, SQ_ / BM, B_);
        scores_kernel<<<grid, 256>>>(Q, K, qlens, klens, wts);
    }
    {
        dim3 grid(SQ_, B_);
        softmax_kernel<<<grid, 256>>>(wts, qlens, klens);
    }
    {
        dim3 grid(DV_ / BN, SQ_ / BM, B_);
        context_kernel<<<grid, 256>>>(wts, V, qlens, klens, ctx);
    }
}

// round 13
// speedup vs baseline: 1.0405x; 1.0405x over previous
#include <cuda_runtime.h>
#include <cuda_bf16.h>
#include <math.h>

#define B_  8
#define SQ_ 2048
#define SK_ 2048
#define D_  1024
#define DV_ 1024
#define SCALE (1.0f/32.0f)

#define BM 128
#define BN 128
#define BK 16
#define AST 20    // A/W smem row stride (words): conflict-free fragment loads
#define VST 136   // V smem row stride (words): conflict-free b-frag loads

__device__ __forceinline__ unsigned f2tf(float x) {
    unsigned u;
    asm("cvt.rna.tf32.f32 %0, %1;" : "=r"(u) : "f"(x));
    return u;
}
__device__ __forceinline__ unsigned u2tf(unsigned r) { return f2tf(__uint_as_float(r)); }

// NOT volatile: pure computation, let ptxas schedule freely.
__device__ __forceinline__ void mma_tf32(float c[4], const unsigned a[4], const unsigned b[2]) {
    asm("mma.sync.aligned.m16n8k8.row.col.f32.tf32.tf32.f32 "
        "{%0,%1,%2,%3}, {%4,%5,%6,%7}, {%8,%9}, {%0,%1,%2,%3};"
        : "+f"(c[0]), "+f"(c[1]), "+f"(c[2]), "+f"(c[3])
        : "r"(a[0]), "r"(a[1]), "r"(a[2]), "r"(a[3]), "r"(b[0]), "r"(b[1]));
}

__device__ __forceinline__ void ldsm4(unsigned& r0, unsigned& r1, unsigned& r2, unsigned& r3,
                                      unsigned addr) {
    asm volatile("ldmatrix.sync.aligned.m8n8.x4.shared.b16 {%0,%1,%2,%3}, [%4];"
                 : "=r"(r0), "=r"(r1), "=r"(r2), "=r"(r3) : "r"(addr));
}

__device__ __forceinline__ unsigned smem_u32(const void* p) {
    return (unsigned)__cvta_generic_to_shared(p);
}

__device__ __forceinline__ void cpa16(void* smem, const void* gmem) {
    unsigned s = (unsigned)__cvta_generic_to_shared(smem);
    asm volatile("cp.async.ca.shared.global [%0], [%1], 16;" :: "r"(s), "l"(gmem));
}
__device__ __forceinline__ void cpa_commit() { asm volatile("cp.async.commit_group;"); }
__device__ __forceinline__ void cpa_wait1()  { asm volatile("cp.async.wait_group 1;"); }
__device__ __forceinline__ void cpa_wait0()  { asm volatile("cp.async.wait_group 0;"); }

// ---------------------------------------------------------------------------
// Kernel 1: raw scores S = (Q @ K^T) * scale (tf32 MMA + ldmatrix frags).
// 128x128 tile, 4 warps as 2x2, warp tile 64x64. 2-stage cp.async pipeline.
// Fragments for both k8 halves loaded up front (reg double-buffer).
// ---------------------------------------------------------------------------
__global__ __launch_bounds__(128, 2) void scores_kernel(
    const float* __restrict__ Q, const float* __restrict__ K,
    const int* __restrict__ qlens, const int* __restrict__ klens,
    float* __restrict__ Sout)
{
    const int b  = blockIdx.z;
    const int q0 = blockIdx.y * BM;
    const int k0 = blockIdx.x * BN;
    const int qlen = qlens[b];
    const int klen = klens[b];
    if (q0 >= qlen || k0 >= klen || k0 > q0 + BM - 1) return;

    __shared__ float As[2][BM][AST];
    __shared__ float Bs[2][BN][AST];

    const int tid  = threadIdx.x;
    const int lane = tid & 31;
    const int wid  = tid >> 5;          // 0..3
    const int wm   = (wid >> 1) * 64;
    const int wn   = (wid & 1) * 64;
    const int g    = lane >> 2;
    const int t    = lane & 3;
    const int sub  = lane >> 3;         // 0..3  (ldmatrix tile index)
    const int j8   = lane & 7;          // row within tile

    const unsigned aBase = smem_u32(As) +
        ((unsigned)((wm + (sub & 1) * 8 + j8) * AST + (sub >> 1) * 4)) * 4u;
    const unsigned bBase = smem_u32(Bs) +
        ((unsigned)((wn + (sub >> 1) * 8 + j8) * AST + (sub & 1) * 4)) * 4u;
    const unsigned stgA = BM * AST * 4u;   // bytes per pipeline stage

    const float* Qb = Q + ((size_t)b * SQ_ + q0) * D_;
    const float* Kb = K + ((size_t)b * SK_ + k0) * D_;

    const int lrow0 = tid >> 2;                 // chunk j: row = lrow0 + 32*j
    const int lc4   = (tid & 3) * 4;

#define ISSUE_S(s, it)                                                     \
    {                                                                      \
        const int kofs = (it) * BK;                                        \
        _Pragma("unroll")                                                  \
        for (int j = 0; j < 4; ++j) {                                      \
            const int row = lrow0 + 32 * j;                                \
            cpa16(&As[s][row][lc4], Qb + (size_t)row * D_ + kofs + lc4);   \
            cpa16(&Bs[s][row][lc4], Kb + (size_t)row * D_ + kofs + lc4);   \
        }                                                                  \
        cpa_commit();                                                      \
    }

    const int NT = D_ / BK;   // 64
    ISSUE_S(0, 0)
    ISSUE_S(1, 1)

    float acc[4][8][4];
#pragma unroll
    for (int i = 0; i < 4; ++i)
#pragma unroll
        for (int j = 0; j < 8; ++j)
#pragma unroll
            for (int c = 0; c < 4; ++c) acc[i][j][c] = 0.f;

    for (int it = 0; it < NT; ++it) {
        if (it < NT - 1) cpa_wait1(); else cpa_wait0();
        __syncthreads();
        const unsigned offA = (it & 1) ? stgA : 0u;

        unsigned a0[4][4], b0[8][2], a1[4][4], b1[8][2];
        // ---- load ALL fragments for both k8 halves first ----
#pragma unroll
        for (int mf = 0; mf < 4; ++mf)
            ldsm4(a0[mf][0], a0[mf][1], a0[mf][2], a0[mf][3],
                  aBase + offA + (unsigned)((mf * 16 * AST) * 4));
#pragma unroll
        for (int nfp = 0; nfp < 4; ++nfp)
            ldsm4(b0[2*nfp][0], b0[2*nfp][1], b0[2*nfp+1][0], b0[2*nfp+1][1],
                  bBase + offA + (unsigned)((nfp * 16 * AST) * 4));
#pragma unroll
        for (int mf = 0; mf < 4; ++mf)
            ldsm4(a1[mf][0], a1[mf][1], a1[mf][2], a1[mf][3],
                  aBase + offA + (unsigned)((mf * 16 * AST + 8) * 4));
#pragma unroll
        for (int nfp = 0; nfp < 4; ++nfp)
            ldsm4(b1[2*nfp][0], b1[2*nfp][1], b1[2*nfp+1][0], b1[2*nfp+1][1],
                  bBase + offA + (unsigned)((nfp * 16 * AST + 8) * 4));

        // ---- ks = 0 ----
#pragma unroll
        for (int mf = 0; mf < 4; ++mf)
#pragma unroll
            for (int i = 0; i < 4; ++i) a0[mf][i] = u2tf(a0[mf][i]);
#pragma unroll
        for (int nf = 0; nf < 8; ++nf) {
            b0[nf][0] = u2tf(b0[nf][0]); b0[nf][1] = u2tf(b0[nf][1]);
        }
#pragma unroll
        for (int mf = 0; mf < 4; ++mf)
#pragma unroll
            for (int nf = 0; nf < 8; ++nf)
                mma_tf32(acc[mf][nf], a0[mf], b0[nf]);

        // ---- ks = 1 ----
#pragma unroll
        for (int mf = 0; mf < 4; ++mf)
#pragma unroll
            for (int i = 0; i < 4; ++i) a1[mf][i] = u2tf(a1[mf][i]);
#pragma unroll
        for (int nf = 0; nf < 8; ++nf) {
            b1[nf][0] = u2tf(b1[nf][0]); b1[nf][1] = u2tf(b1[nf][1]);
        }
#pragma unroll
        for (int mf = 0; mf < 4; ++mf)
#pragma unroll
            for (int nf = 0; nf < 8; ++nf)
                mma_tf32(acc[mf][nf], a1[mf], b1[nf]);

        __syncthreads();
        if (it + 2 < NT) ISSUE_S((it & 1), it + 2)
    }

    float* Sp = Sout + ((size_t)b * SQ_ + q0) * SK_ + k0;
#pragma unroll
    for (int mf = 0; mf < 4; ++mf) {
        const int r0 = wm + mf * 16 + g;
#pragma unroll
        for (int nf = 0; nf < 8; ++nf) {
            const int c0 = wn + nf * 8 + 2 * t;
            float2 v0 = make_float2(acc[mf][nf][0] * SCALE, acc[mf][nf][1] * SCALE);
            float2 v1 = make_float2(acc[mf][nf][2] * SCALE, acc[mf][nf][3] * SCALE);
            *(float2*)(Sp + (size_t)r0 * SK_ + c0)       = v0;
            *(float2*)(Sp + (size_t)(r0 + 8) * SK_ + c0) = v1;
        }
    }
#undef ISSUE_S
}

// ---------------------------------------------------------------------------
// Kernel 2: in-place masked softmax per row; reads only the valid prefix,
// zero-writes everything else.
// ---------------------------------------------------------------------------
__global__ __launch_bounds__(256) void softmax_kernel(
    float* __restrict__ Wio,
    const int* __restrict__ qlens, const int* __restrict__ klens)
{
    const int q = blockIdx.x;
    const int b = blockIdx.y;
    const int tid = threadIdx.x;
    const int lane = tid & 31;
    const int wid = tid >> 5;
    float* row = Wio + ((size_t)b * SQ_ + q) * SK_;

    const int qlen = qlens[b];
    const int klen = klens[b];

    if (q >= qlen) {
        float4 z = make_float4(0.f, 0.f, 0.f, 0.f);
        for (int j = tid; j < SK_ / 4; j += 256) ((float4*)row)[j] = z;
        return;
    }

    const int kk  = min(klen, q + 1);
    const int kq4 = (kk + 3) >> 2;

    __shared__ float buf[SK_];
    __shared__ float red[8];

    float m = -3.402823466e38f;
    for (int j = tid; j < kq4; j += 256) {
        float4 s = ((const float4*)row)[j];
        ((float4*)buf)[j] = s;
        int base = j * 4;
        if (base + 0 < kk) m = fmaxf(m, s.x);
        if (base + 1 < kk) m = fmaxf(m, s.y);
        if (base + 2 < kk) m = fmaxf(m, s.z);
        if (base + 3 < kk) m = fmaxf(m, s.w);
    }
#pragma unroll
    for (int o = 16; o > 0; o >>= 1) m = fmaxf(m, __shfl_xor_sync(0xffffffffu, m, o));
    if (lane == 0) red[wid] = m;
    __syncthreads();
    m = red[0];
#pragma unroll
    for (int w = 1; w < 8; ++w) m = fmaxf(m, red[w]);
    __syncthreads();

    float sum = 0.f;
    for (int j = tid; j < kq4; j += 256) {
        int base = j * 4;
        float4 s = ((const float4*)buf)[j];
        float4 e;
        e.x = (base + 0 < kk) ? __expf(s.x - m) : 0.f;
        e.y = (base + 1 < kk) ? __expf(s.y - m) : 0.f;
        e.z = (base + 2 < kk) ? __expf(s.z - m) : 0.f;
        e.w = (base + 3 < kk) ? __expf(s.w - m) : 0.f;
        ((float4*)buf)[j] = e;
        sum += e.x + e.y + e.z + e.w;
    }
#pragma unroll
    for (int o = 16; o > 0; o >>= 1) sum += __shfl_xor_sync(0xffffffffu, sum, o);
    if (lane == 0) red[wid] = sum;
    __syncthreads();
    float tot = red[0];
#pragma unroll
    for (int w = 1; w < 8; ++w) tot += red[w];
    const float inv = 1.f / tot;

    for (int j = tid; j < kq4; j += 256) {
        float4 e = ((const float4*)buf)[j];
        e.x *= inv; e.y *= inv; e.z *= inv; e.w *= inv;
        ((float4*)row)[j] = e;
    }
    float4 z = make_float4(0.f, 0.f, 0.f, 0.f);
    for (int j = kq4 + tid; j < SK_ / 4; j += 256) ((float4*)row)[j] = z;
}

// ---------------------------------------------------------------------------
// Kernel 3: context = W @ V (tf32 MMA; ldmatrix for W frags, scalar for V).
// 64x64 warp tiles; both k8 halves' fragments loaded up front.
// ---------------------------------------------------------------------------
__global__ __launch_bounds__(128, 2) void context_kernel(
    const float* __restrict__ W, const float* __restrict__ V,
    const int* __restrict__ qlens, const int* __restrict__ klens,
    float* __restrict__ C)
{
    const int b  = blockIdx.z;
    const int q0 = blockIdx.y * BM;
    const int v0 = blockIdx.x * BN;
    const int qlen = qlens[b];
    const int klen = klens[b];

    const int tid  = threadIdx.x;
    float* Cb = C + ((size_t)b * SQ_ + q0) * DV_ + v0;

    if (q0 >= qlen) {
        float4 z = make_float4(0.f, 0.f, 0.f, 0.f);
        for (int idx = tid; idx < BM * BN / 4; idx += 128) {
            const int r = idx / (BN / 4);
            const int c = (idx % (BN / 4)) * 4;
            *(float4*)(Cb + (size_t)r * DV_ + c) = z;
        }
        return;
    }

    __shared__ float Ws[2][BM][AST];
    __shared__ float Vs[2][BK][VST];

    const int lane = tid & 31;
    const int wid  = tid >> 5;
    const int wm   = (wid >> 1) * 64;
    const int wn   = (wid & 1) * 64;
    const int g    = lane >> 2;
    const int t    = lane & 3;
    const int sub  = lane >> 3;
    const int j8   = lane & 7;

    const unsigned aBase = smem_u32(Ws) +
        ((unsigned)((wm + (sub & 1) * 8 + j8) * AST + (sub >> 1) * 4)) * 4u;
    const unsigned stgA = BM * AST * 4u;

    const float* Wb = W + ((size_t)b * SQ_ + q0) * SK_;
    const float* Vb = V + (size_t)b * SK_ * DV_ + v0;

    const int lrow0 = tid >> 2;             // W loader: rows lrow0+32j
    const int lc4   = (tid & 3) * 4;
    const int vk0   = tid >> 5;             // V loader: k rows vk0+4j
    const int vn4   = (tid & 31) * 4;

#define ISSUE_C(s, it)                                                       \
    {                                                                        \
        const int kofs = (it) * BK;                                          \
        _Pragma("unroll")                                                    \
        for (int j = 0; j < 4; ++j) {                                        \
            const int row = lrow0 + 32 * j;                                  \
            cpa16(&Ws[s][row][lc4], Wb + (size_t)row * SK_ + kofs + lc4);    \
        }                                                                    \
        _Pragma("unroll")                                                    \
        for (int j = 0; j < 4; ++j) {                                        \
            const int kr = vk0 + 4 * j;                                      \
            cpa16(&Vs[s][kr][vn4], Vb + (size_t)(kofs + kr) * DV_ + vn4);    \
        }                                                                    \
        cpa_commit();                                                        \
    }

    const int kend = min(klen, q0 + BM);
    const int NT   = (kend + BK - 1) / BK;   // >= 1

    ISSUE_C(0, 0)
    if (NT > 1) ISSUE_C(1, 1)

    float acc[4][8][4];
#pragma unroll
    for (int i = 0; i < 4; ++i)
#pragma unroll
        for (int j = 0; j < 8; ++j)
#pragma unroll
            for (int c = 0; c < 4; ++c) acc[i][j][c] = 0.f;

    for (int it = 0; it < NT; ++it) {
        if (it < NT - 1) cpa_wait1(); else cpa_wait0();
        __syncthreads();
        const int buf = it & 1;
        const unsigned offA = buf ? stgA : 0u;

        unsigned a0[4][4], a1[4][4];
        float v0f[8][2], v1f[8][2];
        // ---- load ALL fragments for both k8 halves ----
#pragma unroll
        for (int mf = 0; mf < 4; ++mf)
            ldsm4(a0[mf][0], a0[mf][1], a0[mf][2], a0[mf][3],
                  aBase + offA + (unsigned)((mf * 16 * AST) * 4));
#pragma unroll
        for (int mf = 0; mf < 4; ++mf)
            ldsm4(a1[mf][0], a1[mf][1], a1[mf][2], a1[mf][3],
                  aBase + offA + (unsigned)((mf * 16 * AST + 8) * 4));
#pragma unroll
        for (int nf = 0; nf < 8; ++nf) {
            const int col = wn + nf * 8;
            v0f[nf][0] = Vs[buf][t][col + g];
            v0f[nf][1] = Vs[buf][t + 4][col + g];
            v1f[nf][0] = Vs[buf][t + 8][col + g];
            v1f[nf][1] = Vs[buf][t + 12][col + g];
        }

        // ---- ks = 0 ----
        {
            unsigned bb[8][2];
#pragma unroll
            for (int mf = 0; mf < 4; ++mf)
#pragma unroll
                for (int i = 0; i < 4; ++i) a0[mf][i] = u2tf(a0[mf][i]);
#pragma unroll
            for (int nf = 0; nf < 8; ++nf) {
                bb[nf][0] = f2tf(v0f[nf][0]); bb[nf][1] = f2tf(v0f[nf][1]);
            }
#pragma unroll
            for (int mf = 0; mf < 4; ++mf)
#pragma unroll
                for (int nf = 0; nf < 8; ++nf)
                    mma_tf32(acc[mf][nf], a0[mf], bb[nf]);
        }
        // ---- ks = 1 ----
        {
            unsigned bb[8][2];
#pragma unroll
            for (int mf = 0; mf < 4; ++mf)
#pragma unroll
                for (int i = 0; i < 4; ++i) a1[mf][i] = u2tf(a1[mf][i]);
#pragma unroll
            for (int nf = 0; nf < 8; ++nf) {
                bb[nf][0] = f2tf(v1f[nf][0]); bb[nf][1] = f2tf(v1f[nf][1]);
            }
#pragma unroll
            for (int mf = 0; mf < 4; ++mf)
#pragma unroll
                for (int nf = 0; nf < 8; ++nf)
                    mma_tf32(acc[mf][nf], a1[mf], bb[nf]);
        }

        __syncthreads();
        if (it + 2 < NT) ISSUE_C(buf, it + 2)
    }

#pragma unroll
    for (int mf = 0; mf < 4; ++mf) {
        const int r0 = wm + mf * 16 + g;
#pragma unroll
        for (int nf = 0; nf < 8; ++nf) {
            const int c0 = wn + nf * 8 + 2 * t;
            float2 v0r = make_float2(acc[mf][nf][0], acc[mf][nf][1]);
            float2 v1r = make_float2(acc[mf][nf][2], acc[mf][nf][3]);
            *(float2*)(Cb + (size_t)r0 * DV_ + c0)       = v0r;
            *(float2*)(Cb + (size_t)(r0 + 8) * DV_ + c0) = v1r;
        }
    }
#undef ISSUE_C
}

// ---------------------------------------------------------------------------
extern "C" void kernel_launch(void* const* d_in, const int* in_sizes, int n_in,
                              void* d_out, int out_size)
{
    const float* Q = (const float*)d_in[0];
    const float* K = (const float*)d_in[1];
    const float* V = (const float*)d_in[2];
    const int* qlens = (const int*)d_in[3];
    const int* klens = (const int*)d_in[4];

    float* ctx = (float*)d_out;
    float* wts = (float*)d_out + (size_t)B_ * SQ_ * DV_;

    {
        dim3 grid(SK_ / BN, SQ_ / BM, B_);
        scores_kernel<<<grid, 128>>>(Q, K, qlens, klens, wts);
    }
    {
        dim3 grid(SQ_, B_);
        softmax_kernel<<<grid, 256>>>(wts, qlens, klens);
    }
    {
        dim3 grid(DV_ / BN, SQ_ / BM, B_);
        context_kernel<<<grid, 128>>>(wts, V, qlens, klens, ctx);
    }
}

// round 15
// speedup vs baseline: 1.1907x; 1.1444x over previous
#include <cuda_runtime.h>
#include <cuda_bf16.h>
#include <math.h>

#define B_  8
#define SQ_ 2048
#define SK_ 2048
#define D_  1024
#define DV_ 1024
#define SCALE (1.0f/32.0f)

#define BM 128
#define BN 128
#define BK 32
#define AST 36    // BK + 4 pad: conflict-free ldmatrix phases
#define VST 136   // V smem row stride (words): conflict-free b-frag loads

__device__ __forceinline__ unsigned f2tf(float x) {
    unsigned u;
    asm("cvt.rna.tf32.f32 %0, %1;" : "=r"(u) : "f"(x));
    return u;
}
__device__ __forceinline__ unsigned u2tf(unsigned r) { return f2tf(__uint_as_float(r)); }

// Pure computation: no volatile, let ptxas schedule.
__device__ __forceinline__ void mma_tf32(float c[4], const unsigned a[4], const unsigned b[2]) {
    asm("mma.sync.aligned.m16n8k8.row.col.f32.tf32.tf32.f32 "
        "{%0,%1,%2,%3}, {%4,%5,%6,%7}, {%8,%9}, {%0,%1,%2,%3};"
        : "+f"(c[0]), "+f"(c[1]), "+f"(c[2]), "+f"(c[3])
        : "r"(a[0]), "r"(a[1]), "r"(a[2]), "r"(a[3]), "r"(b[0]), "r"(b[1]));
}

__device__ __forceinline__ void ldsm4(unsigned& r0, unsigned& r1, unsigned& r2, unsigned& r3,
                                      unsigned addr) {
    asm volatile("ldmatrix.sync.aligned.m8n8.x4.shared.b16 {%0,%1,%2,%3}, [%4];"
                 : "=r"(r0), "=r"(r1), "=r"(r2), "=r"(r3) : "r"(addr));
}

__device__ __forceinline__ unsigned smem_u32(const void* p) {
    return (unsigned)__cvta_generic_to_shared(p);
}

__device__ __forceinline__ void cpa16(void* smem, const void* gmem) {
    unsigned s = (unsigned)__cvta_generic_to_shared(smem);
    asm volatile("cp.async.ca.shared.global [%0], [%1], 16;" :: "r"(s), "l"(gmem));
}
__device__ __forceinline__ void cpa_commit() { asm volatile("cp.async.commit_group;"); }
__device__ __forceinline__ void cpa_wait1()  { asm volatile("cp.async.wait_group 1;"); }
__device__ __forceinline__ void cpa_wait0()  { asm volatile("cp.async.wait_group 0;"); }

// ---------------------------------------------------------------------------
// Kernel 1: raw scores S = (Q @ K^T) * scale (tf32 MMA + ldmatrix frags).
// 128x128 tile, 4 warps as 2x2, warp tile 64x64. 2-stage cp.async, BK=32.
// ---------------------------------------------------------------------------
__global__ __launch_bounds__(128, 2) void scores_kernel(
    const float* __restrict__ Q, const float* __restrict__ K,
    const int* __restrict__ qlens, const int* __restrict__ klens,
    float* __restrict__ Sout)
{
    const int b  = blockIdx.z;
    const int q0 = blockIdx.y * BM;
    const int k0 = blockIdx.x * BN;
    const int qlen = qlens[b];
    const int klen = klens[b];
    if (q0 >= qlen || k0 >= klen || k0 > q0 + BM - 1) return;

    __shared__ float As[2][BM][AST];
    __shared__ float Bs[2][BN][AST];

    const int tid  = threadIdx.x;
    const int lane = tid & 31;
    const int wid  = tid >> 5;          // 0..3
    const int wm   = (wid >> 1) * 64;
    const int wn   = (wid & 1) * 64;
    const int g    = lane >> 2;
    const int t    = lane & 3;
    const int sub  = lane >> 3;         // 0..3  (ldmatrix tile index)
    const int j8   = lane & 7;          // row within tile

    const unsigned aBase = smem_u32(As) +
        ((unsigned)((wm + (sub & 1) * 8 + j8) * AST + (sub >> 1) * 4)) * 4u;
    const unsigned bBase = smem_u32(Bs) +
        ((unsigned)((wn + (sub >> 1) * 8 + j8) * AST + (sub & 1) * 4)) * 4u;
    const unsigned stgA = BM * AST * 4u;   // bytes per pipeline stage

    const float* Qb = Q + ((size_t)b * SQ_ + q0) * D_;
    const float* Kb = K + ((size_t)b * SK_ + k0) * D_;

    // loader: 8 chunks/row (32 floats), 1024 chunks per array, 8 per thread
    const int lrow0 = tid >> 3;                 // chunk j: row = lrow0 + 16*j
    const int lc4   = (tid & 7) * 4;

#define ISSUE_S(s, it)                                                     \
    {                                                                      \
        const int kofs = (it) * BK;                                        \
        _Pragma("unroll")                                                  \
        for (int j = 0; j < 8; ++j) {                                      \
            const int row = lrow0 + 16 * j;                                \
            cpa16(&As[s][row][lc4], Qb + (size_t)row * D_ + kofs + lc4);   \
            cpa16(&Bs[s][row][lc4], Kb + (size_t)row * D_ + kofs + lc4);   \
        }                                                                  \
        cpa_commit();                                                      \
    }

    const int NT = D_ / BK;   // 32
    ISSUE_S(0, 0)
    ISSUE_S(1, 1)

    float acc[4][8][4];
#pragma unroll
    for (int i = 0; i < 4; ++i)
#pragma unroll
        for (int j = 0; j < 8; ++j)
#pragma unroll
            for (int c = 0; c < 4; ++c) acc[i][j][c] = 0.f;

    for (int it = 0; it < NT; ++it) {
        if (it < NT - 1) cpa_wait1(); else cpa_wait0();
        __syncthreads();
        const unsigned offA = (it & 1) ? stgA : 0u;
#pragma unroll
        for (int ks = 0; ks < 4; ++ks) {
            unsigned a[4][4], bb[8][2];
#pragma unroll
            for (int mf = 0; mf < 4; ++mf) {
                unsigned r0, r1, r2, r3;
                ldsm4(r0, r1, r2, r3,
                      aBase + offA + (unsigned)((mf * 16 * AST + ks * 8) * 4));
                a[mf][0] = u2tf(r0); a[mf][1] = u2tf(r1);
                a[mf][2] = u2tf(r2); a[mf][3] = u2tf(r3);
            }
#pragma unroll
            for (int nfp = 0; nfp < 4; ++nfp) {
                unsigned r0, r1, r2, r3;
                ldsm4(r0, r1, r2, r3,
                      bBase + offA + (unsigned)((nfp * 16 * AST + ks * 8) * 4));
                bb[2*nfp][0]   = u2tf(r0); bb[2*nfp][1]   = u2tf(r1);
                bb[2*nfp+1][0] = u2tf(r2); bb[2*nfp+1][1] = u2tf(r3);
            }
#pragma unroll
            for (int mf = 0; mf < 4; ++mf)
#pragma unroll
                for (int nf = 0; nf < 8; ++nf)
                    mma_tf32(acc[mf][nf], a[mf], bb[nf]);
        }
        __syncthreads();
        if (it + 2 < NT) ISSUE_S((it & 1), it + 2)
    }

    float* Sp = Sout + ((size_t)b * SQ_ + q0) * SK_ + k0;
#pragma unroll
    for (int mf = 0; mf < 4; ++mf) {
        const int r0 = wm + mf * 16 + g;
#pragma unroll
        for (int nf = 0; nf < 8; ++nf) {
            const int c0 = wn + nf * 8 + 2 * t;
            float2 v0 = make_float2(acc[mf][nf][0] * SCALE, acc[mf][nf][1] * SCALE);
            float2 v1 = make_float2(acc[mf][nf][2] * SCALE, acc[mf][nf][3] * SCALE);
            *(float2*)(Sp + (size_t)r0 * SK_ + c0)       = v0;
            *(float2*)(Sp + (size_t)(r0 + 8) * SK_ + c0) = v1;
        }
    }
#undef ISSUE_S
}

// ---------------------------------------------------------------------------
// Kernel 2: in-place masked softmax per row; reads only the valid prefix,
// zero-writes everything else.
// ---------------------------------------------------------------------------
__global__ __launch_bounds__(256) void softmax_kernel(
    float* __restrict__ Wio,
    const int* __restrict__ qlens, const int* __restrict__ klens)
{
    const int q = blockIdx.x;
    const int b = blockIdx.y;
    const int tid = threadIdx.x;
    const int lane = tid & 31;
    const int wid = tid >> 5;
    float* row = Wio + ((size_t)b * SQ_ + q) * SK_;

    const int qlen = qlens[b];
    const int klen = klens[b];

    if (q >= qlen) {
        float4 z = make_float4(0.f, 0.f, 0.f, 0.f);
        for (int j = tid; j < SK_ / 4; j += 256) ((float4*)row)[j] = z;
        return;
    }

    const int kk  = min(klen, q + 1);
    const int kq4 = (kk + 3) >> 2;

    __shared__ float buf[SK_];
    __shared__ float red[8];

    float m = -3.402823466e38f;
    for (int j = tid; j < kq4; j += 256) {
        float4 s = ((const float4*)row)[j];
        ((float4*)buf)[j] = s;
        int base = j * 4;
        if (base + 0 < kk) m = fmaxf(m, s.x);
        if (base + 1 < kk) m = fmaxf(m, s.y);
        if (base + 2 < kk) m = fmaxf(m, s.z);
        if (base + 3 < kk) m = fmaxf(m, s.w);
    }
#pragma unroll
    for (int o = 16; o > 0; o >>= 1) m = fmaxf(m, __shfl_xor_sync(0xffffffffu, m, o));
    if (lane == 0) red[wid] = m;
    __syncthreads();
    m = red[0];
#pragma unroll
    for (int w = 1; w < 8; ++w) m = fmaxf(m, red[w]);
    __syncthreads();

    float sum = 0.f;
    for (int j = tid; j < kq4; j += 256) {
        int base = j * 4;
        float4 s = ((const float4*)buf)[j];
        float4 e;
        e.x = (base + 0 < kk) ? __expf(s.x - m) : 0.f;
        e.y = (base + 1 < kk) ? __expf(s.y - m) : 0.f;
        e.z = (base + 2 < kk) ? __expf(s.z - m) : 0.f;
        e.w = (base + 3 < kk) ? __expf(s.w - m) : 0.f;
        ((float4*)buf)[j] = e;
        sum += e.x + e.y + e.z + e.w;
    }
#pragma unroll
    for (int o = 16; o > 0; o >>= 1) sum += __shfl_xor_sync(0xffffffffu, sum, o);
    if (lane == 0) red[wid] = sum;
    __syncthreads();
    float tot = red[0];
#pragma unroll
    for (int w = 1; w < 8; ++w) tot += red[w];
    const float inv = 1.f / tot;

    for (int j = tid; j < kq4; j += 256) {
        float4 e = ((const float4*)buf)[j];
        e.x *= inv; e.y *= inv; e.z *= inv; e.w *= inv;
        ((float4*)row)[j] = e;
    }
    float4 z = make_float4(0.f, 0.f, 0.f, 0.f);
    for (int j = kq4 + tid; j < SK_ / 4; j += 256) ((float4*)row)[j] = z;
}

// ---------------------------------------------------------------------------
// Kernel 3: context = W @ V (tf32 MMA; ldmatrix for W frags, scalar for V).
// 64x64 warp tiles, BK=32, 2-stage; K clamped to valid prefix.
// ---------------------------------------------------------------------------
__global__ __launch_bounds__(128, 2) void context_kernel(
    const float* __restrict__ W, const float* __restrict__ V,
    const int* __restrict__ qlens, const int* __restrict__ klens,
    float* __restrict__ C)
{
    const int b  = blockIdx.z;
    const int q0 = blockIdx.y * BM;
    const int v0 = blockIdx.x * BN;
    const int qlen = qlens[b];
    const int klen = klens[b];

    const int tid  = threadIdx.x;
    float* Cb = C + ((size_t)b * SQ_ + q0) * DV_ + v0;

    if (q0 >= qlen) {
        float4 z = make_float4(0.f, 0.f, 0.f, 0.f);
        for (int idx = tid; idx < BM * BN / 4; idx += 128) {
            const int r = idx / (BN / 4);
            const int c = (idx % (BN / 4)) * 4;
            *(float4*)(Cb + (size_t)r * DV_ + c) = z;
        }
        return;
    }

    __shared__ float Ws[2][BM][AST];
    __shared__ float Vs[2][BK][VST];

    const int lane = tid & 31;
    const int wid  = tid >> 5;
    const int wm   = (wid >> 1) * 64;
    const int wn   = (wid & 1) * 64;
    const int g    = lane >> 2;
    const int t    = lane & 3;
    const int sub  = lane >> 3;
    const int j8   = lane & 7;

    const unsigned aBase = smem_u32(Ws) +
        ((unsigned)((wm + (sub & 1) * 8 + j8) * AST + (sub >> 1) * 4)) * 4u;
    const unsigned stgA = BM * AST * 4u;

    const float* Wb = W + ((size_t)b * SQ_ + q0) * SK_;
    const float* Vb = V + (size_t)b * SK_ * DV_ + v0;

    const int lrow0 = tid >> 3;             // W loader: rows lrow0+16j
    const int lc4   = (tid & 7) * 4;
    const int vk0   = tid >> 5;             // V loader: k rows vk0+4j (j=0..7)
    const int vn4   = (tid & 31) * 4;

#define ISSUE_C(s, it)                                                       \
    {                                                                        \
        const int kofs = (it) * BK;                                          \
        _Pragma("unroll")                                                    \
        for (int j = 0; j < 8; ++j) {                                        \
            const int row = lrow0 + 16 * j;                                  \
            cpa16(&Ws[s][row][lc4], Wb + (size_t)row * SK_ + kofs + lc4);    \
        }                                                                    \
        _Pragma("unroll")                                                    \
        for (int j = 0; j < 8; ++j) {                                        \
            const int kr = vk0 + 4 * j;                                      \
            cpa16(&Vs[s][kr][vn4], Vb + (size_t)(kofs + kr) * DV_ + vn4);    \
        }                                                                    \
        cpa_commit();                                                        \
    }

    const int kend = min(klen, q0 + BM);
    const int NT   = (kend + BK - 1) / BK;   // >= 1

    ISSUE_C(0, 0)
    if (NT > 1) ISSUE_C(1, 1)

    float acc[4][8][4];
#pragma unroll
    for (int i = 0; i < 4; ++i)
#pragma unroll
        for (int j = 0; j < 8; ++j)
#pragma unroll
            for (int c = 0; c < 4; ++c) acc[i][j][c] = 0.f;

    for (int it = 0; it < NT; ++it) {
        if (it < NT - 1) cpa_wait1(); else cpa_wait0();
        __syncthreads();
        const int buf = it & 1;
        const unsigned offA = buf ? stgA : 0u;
#pragma unroll
        for (int ks = 0; ks < 4; ++ks) {
            const int kc = ks * 8 + t;
            unsigned a[4][4], bb[8][2];
#pragma unroll
            for (int mf = 0; mf < 4; ++mf) {
                unsigned r0, r1, r2, r3;
                ldsm4(r0, r1, r2, r3,
                      aBase + offA + (unsigned)((mf * 16 * AST + ks * 8) * 4));
                a[mf][0] = u2tf(r0); a[mf][1] = u2tf(r1);
                a[mf][2] = u2tf(r2); a[mf][3] = u2tf(r3);
            }
#pragma unroll
            for (int nf = 0; nf < 8; ++nf) {
                const int col = wn + nf * 8;
                bb[nf][0] = f2tf(Vs[buf][kc][col + g]);
                bb[nf][1] = f2tf(Vs[buf][kc + 4][col + g]);
            }
#pragma unroll
            for (int mf = 0; mf < 4; ++mf)
#pragma unroll
                for (int nf = 0; nf < 8; ++nf)
                    mma_tf32(acc[mf][nf], a[mf], bb[nf]);
        }
        __syncthreads();
        if (it + 2 < NT) ISSUE_C(buf, it + 2)
    }

#pragma unroll
    for (int mf = 0; mf < 4; ++mf) {
        const int r0 = wm + mf * 16 + g;
#pragma unroll
        for (int nf = 0; nf < 8; ++nf) {
            const int c0 = wn + nf * 8 + 2 * t;
            float2 v0r = make_float2(acc[mf][nf][0], acc[mf][nf][1]);
            float2 v1r = make_float2(acc[mf][nf][2], acc[mf][nf][3]);
            *(float2*)(Cb + (size_t)r0 * DV_ + c0)       = v0r;
            *(float2*)(Cb + (size_t)(r0 + 8) * DV_ + c0) = v1r;
        }
    }
#undef ISSUE_C
}

// ---------------------------------------------------------------------------
extern "C" void kernel_launch(void* const* d_in, const int* in_sizes, int n_in,
                              void* d_out, int out_size)
{
    const float* Q = (const float*)d_in[0];
    const float* K = (const float*)d_in[1];
    const float* V = (const float*)d_in[2];
    const int* qlens = (const int*)d_in[3];
    const int* klens = (const int*)d_in[4];

    float* ctx = (float*)d_out;
    float* wts = (float*)d_out + (size_t)B_ * SQ_ * DV_;

    {
        dim3 grid(SK_ / BN, SQ_ / BM, B_);
        scores_kernel<<<grid, 128>>>(Q, K, qlens, klens, wts);
    }
    {
        dim3 grid(SQ_, B_);
        softmax_kernel<<<grid, 256>>>(wts, qlens, klens);
    }
    {
        dim3 grid(DV_ / BN, SQ_ / BM, B_);
        context_kernel<<<grid, 128>>>(wts, V, qlens, klens, ctx);
    }
}